// round 9
// baseline (speedup 1.0000x reference)
#include <cuda_runtime.h>
#include <cuda_bf16.h>
#include <cstdint>

#define R 4096
#define F 256
#define K 8
#define CMIN 1e-6f
#define CMAX 1e6f

#define BM 128
#define BN 128
#define TILE_B 16384               // one 128row x 128B bf16 tile (BK=64)
#define A_SMEM (4 * TILE_B + 1024)

// Scratch (static device globals — no runtime allocation)
__device__ __align__(16) float g_base[(size_t)R * (size_t)R];  // 64 MB
__device__ __align__(16) float g_S[K * R];
__device__ __align__(16) float g_rs[4 * R];     // sx1 | n2x1 | sx2 | n2x2
__device__ __align__(16) float g_kp[6 * K];     // akt|bkt|ekc2|lo|hi|nw
__device__ __align__(16) __nv_bfloat16 g_x1h[R * F];
__device__ __align__(16) __nv_bfloat16 g_x1l[R * F];
__device__ __align__(16) __nv_bfloat16 g_x2h[R * F];
__device__ __align__(16) __nv_bfloat16 g_x2l[R * F];

__device__ __forceinline__ uint32_t smem_u32(const void* p) {
    uint32_t a;
    asm("{ .reg .u64 t; cvta.to.shared.u64 t, %1; cvt.u32.u64 %0, t; }"
        : "=r"(a) : "l"(p));
    return a;
}
__device__ __forceinline__ float ex2f(float x) {
    float y;
    asm("ex2.approx.ftz.f32 %0, %1;" : "=f"(y) : "f"(x));
    return y;
}
// e^kv for kv in [0,1]: degree-5 Taylor at 0.5, coeffs e^0.5/i!.
// max abs error ~3.6e-5 (relative <=3.6e-5 since e^kv >= 1).
__device__ __forceinline__ float exp_unit(float kv) {
    float t = kv - 0.5f;
    float p = 0.013739343922501068f;
    p = fmaf(p, t, 0.06869671961250534f);
    p = fmaf(p, t, 0.27478687845002137f);
    p = fmaf(p, t, 0.8243606353500641f);
    p = fmaf(p, t, 1.6487212707001282f);
    p = fmaf(p, t, 1.6487212707001282f);
    return p;
}
__device__ __forceinline__ void ldsm_x4(uint32_t* r, uint32_t addr) {
    asm volatile("ldmatrix.sync.aligned.m8n8.x4.shared.b16 {%0,%1,%2,%3}, [%4];"
                 : "=r"(r[0]), "=r"(r[1]), "=r"(r[2]), "=r"(r[3]) : "r"(addr));
}
__device__ __forceinline__ void mma16816(float* c, const uint32_t* a,
                                         uint32_t b0, uint32_t b1) {
    asm volatile(
        "mma.sync.aligned.m16n8k16.row.col.f32.bf16.bf16.f32 "
        "{%0,%1,%2,%3}, {%4,%5,%6,%7}, {%8,%9}, {%0,%1,%2,%3};"
        : "+f"(c[0]), "+f"(c[1]), "+f"(c[2]), "+f"(c[3])
        : "r"(a[0]), "r"(a[1]), "r"(a[2]), "r"(a[3]), "r"(b0), "r"(b1));
}

// ---------------------------------------------------------------------------
// Per-k constants. arg = dist*ekc2, ekc2 = -log2e/(2 sigma^2) < 0.
// kv = ex2(arg); e^kv = exp_unit(kv). Clamp arg in [CMAX*ekc2, CMIN*ekc2].
__global__ void params_kernel(const float* __restrict__ sig,
                              const float* __restrict__ mean,
                              const float* __restrict__ sp) {
    if (threadIdx.x == 0) {
        const float L2E = 1.4426950408889634f;
        float w[K];
        float m = -3.4e38f;
        #pragma unroll
        for (int k = 0; k < K; k++) {
            float v = 1.0f / (sp[k] * sp[k]);
            w[k] = v;
            if (v > m) m = v;
        }
        float s = 0.0f;
        #pragma unroll
        for (int k = 0; k < K; k++) { w[k] = __expf(w[k] - m); s += w[k]; }
        float inv_s = 1.0f / s;
        #pragma unroll
        for (int k = 0; k < K; k++) {
            float ekc2 = -L2E / (2.0f * sig[k] * sig[k]);
            float ak   = -2.0f * mean[k];
            float bk   = (float)F * mean[k] * mean[k];
            g_kp[k]         = ak * ekc2;          // akt
            g_kp[K + k]     = bk * ekc2;          // bkt
            g_kp[2 * K + k] = ekc2;
            g_kp[3 * K + k] = CMAX * ekc2;        // lo
            g_kp[4 * K + k] = CMIN * ekc2;        // hi
            g_kp[5 * K + k] = w[k] * inv_s;       // normalized weight
        }
    }
}

__global__ void zero_S_kernel() {
    int i = blockIdx.x * blockDim.x + threadIdx.x;
    if (i < K * R) g_S[i] = 0.0f;
}

// Split fp32 -> bf16 hi + bf16 lo (x ≈ hi + lo)
__global__ void split_kernel(const float* __restrict__ x1,
                             const float* __restrict__ x2) {
    int i = blockIdx.x * blockDim.x + threadIdx.x;
    if (i >= R * F / 4) return;
    float4 v1 = ((const float4*)x1)[i];
    float4 v2 = ((const float4*)x2)[i];
    const float* a = (const float*)&v1;
    const float* b = (const float*)&v2;
    #pragma unroll
    for (int e = 0; e < 4; e++) {
        __nv_bfloat16 h = __float2bfloat16(a[e]);
        g_x1h[i * 4 + e] = h;
        g_x1l[i * 4 + e] = __float2bfloat16(a[e] - __bfloat162float(h));
        h = __float2bfloat16(b[e]);
        g_x2h[i * 4 + e] = h;
        g_x2l[i * 4 + e] = __float2bfloat16(b[e] - __bfloat162float(h));
    }
}

// Row sums and squared norms of x1 and x2 (one warp per row).
__global__ void stats_kernel(const float* __restrict__ x1,
                             const float* __restrict__ x2) {
    int w = blockIdx.x * (blockDim.x >> 5) + (threadIdx.x >> 5);
    int lane = threadIdx.x & 31;
    if (w >= 2 * R) return;
    const float* x = (w < R) ? x1 : x2;
    int row = (w < R) ? w : (w - R);
    float s = 0.0f, q = 0.0f;
    #pragma unroll
    for (int i = 0; i < F / 32; i++) {
        float v = x[(size_t)row * F + lane + i * 32];
        s += v;
        q = fmaf(v, v, q);
    }
    #pragma unroll
    for (int o = 16; o > 0; o >>= 1) {
        s += __shfl_xor_sync(0xFFFFFFFFu, s, o);
        q += __shfl_xor_sync(0xFFFFFFFFu, q, o);
    }
    if (lane == 0) {
        int off = (w < R) ? 0 : 2 * R;
        g_rs[off + row]     = s;
        g_rs[off + R + row] = q;
    }
}

// ---------------------------------------------------------------------------
// Kernel A: 128x128 tile, bf16 split-GEMM (hh+hl+lh) via mma.sync m16n8k16.
// 8 warps in 2(m) x 4(n) grid, 64x32 per warp, fp32 register accumulators.
// Epilogue: base transform + store + exp(kv) S accumulation.
__global__ void __launch_bounds__(256, 2)
kernelA() {
    extern __shared__ char dynsmem[];
    __shared__ float skp[6 * K];

    const int tid  = threadIdx.x;
    const int wid  = tid >> 5;
    const int lane = tid & 31;
    const int wm = wid & 1;          // m position (0..1) -> 64 rows
    const int wn = wid >> 1;         // n position (0..3) -> 32 cols
    const int ln15 = lane & 15;
    const int hi16 = lane >> 4;
    const int r0 = blockIdx.y * BM;
    const int c0 = blockIdx.x * BN;

    const uint32_t dsb = smem_u32(dynsmem);
    const uint32_t tiles_u = (dsb + 1023u) & ~1023u;
    char* tiles = dynsmem + (tiles_u - dsb);

    if (tid < 6 * K) skp[tid] = g_kp[tid];

    // loader mapping: 128 rows x 64 bf16 tiles, SW128 swizzle
    const int lrow  = tid >> 1;
    const int lcol0 = (tid & 1) * 32;
    const __nv_bfloat16* pah = g_x1h + (size_t)(r0 + lrow) * F + lcol0;
    const __nv_bfloat16* pal = g_x1l + (size_t)(r0 + lrow) * F + lcol0;
    const __nv_bfloat16* pbh = g_x2h + (size_t)(c0 + lrow) * F + lcol0;
    const __nv_bfloat16* pbl = g_x2l + (size_t)(c0 + lrow) * F + lcol0;

    // ldmatrix base addresses (row part; chunk xor added per k-step)
    const uint32_t a_row = (uint32_t)(wm * 64 + ln15) * 128u;
    const uint32_t b_row = (uint32_t)(wn * 32 + ln15) * 128u;
    const uint32_t ah_base = tiles_u + 0 * TILE_B + a_row;
    const uint32_t al_base = tiles_u + 1 * TILE_B + a_row;
    const uint32_t bh_base = tiles_u + 2 * TILE_B + b_row;
    const uint32_t bl_base = tiles_u + 3 * TILE_B + b_row;

    float acc[4][4][4];
    #pragma unroll
    for (int i = 0; i < 4; i++)
        #pragma unroll
        for (int j = 0; j < 4; j++)
            #pragma unroll
            for (int c = 0; c < 4; c++) acc[i][j][c] = 0.0f;

    for (int kc = 0; kc < 4; kc++) {
        const int k0 = kc * 64;
        __syncthreads();
        #pragma unroll
        for (int j = 0; j < 4; j++) {
            uint32_t boff = lrow * 128 + (lcol0 + j * 8) * 2;
            uint32_t sw = boff ^ ((boff >> 3) & 0x70);
            *(uint4*)(tiles + 0 * TILE_B + sw) = *(const uint4*)(pah + k0 + j * 8);
            *(uint4*)(tiles + 1 * TILE_B + sw) = *(const uint4*)(pal + k0 + j * 8);
            *(uint4*)(tiles + 2 * TILE_B + sw) = *(const uint4*)(pbh + k0 + j * 8);
            *(uint4*)(tiles + 3 * TILE_B + sw) = *(const uint4*)(pbl + k0 + j * 8);
        }
        __syncthreads();

        #pragma unroll
        for (int ks = 0; ks < 4; ks++) {
            const uint32_t q = (uint32_t)(((ks * 2 + hi16) ^ (ln15 & 7)) * 16);
            uint32_t ah[4][4], bh[2][4], bl[2][4];
            #pragma unroll
            for (int mf = 0; mf < 4; mf++)
                ldsm_x4(ah[mf], ah_base + q + mf * 2048);
            #pragma unroll
            for (int n2 = 0; n2 < 2; n2++)
                ldsm_x4(bh[n2], bh_base + q + n2 * 2048);
            #pragma unroll
            for (int n2 = 0; n2 < 2; n2++)
                ldsm_x4(bl[n2], bl_base + q + n2 * 2048);

            // hh
            #pragma unroll
            for (int mf = 0; mf < 4; mf++)
                #pragma unroll
                for (int nf = 0; nf < 4; nf++)
                    mma16816(acc[mf][nf], ah[mf],
                             bh[nf >> 1][nf & 1], bh[nf >> 1][(nf & 1) + 2]);
            // hl
            #pragma unroll
            for (int mf = 0; mf < 4; mf++)
                #pragma unroll
                for (int nf = 0; nf < 4; nf++)
                    mma16816(acc[mf][nf], ah[mf],
                             bl[nf >> 1][nf & 1], bl[nf >> 1][(nf & 1) + 2]);
            // lh (A-lo overwrites A-hi registers)
            #pragma unroll
            for (int mf = 0; mf < 4; mf++)
                ldsm_x4(ah[mf], al_base + q + mf * 2048);
            #pragma unroll
            for (int mf = 0; mf < 4; mf++)
                #pragma unroll
                for (int nf = 0; nf < 4; nf++)
                    mma16816(acc[mf][nf], ah[mf],
                             bh[nf >> 1][nf & 1], bh[nf >> 1][(nf & 1) + 2]);
        }
    }

    // ---- epilogue ----
    // fragment layout: elem (mf, nf, half, e):
    //   row = r0 + wm*64 + mf*16 + half*8 + lane/4
    //   col = c0 + wn*32 + nf*8 + (lane&3)*2 + e
    const int rbase = r0 + wm * 64 + (lane >> 2);
    const int cbase = c0 + wn * 32 + (lane & 3) * 2;

    float sx1r8[8], n21r8[8];
    #pragma unroll
    for (int i = 0; i < 8; i++) {
        int row = rbase + (i >> 1) * 16 + (i & 1) * 8;
        sx1r8[i] = g_rs[row];
        n21r8[i] = g_rs[R + row];
    }
    float n22c[8], s2c[8];
    #pragma unroll
    for (int nf = 0; nf < 4; nf++) {
        float2 n2 = *(const float2*)&g_rs[3 * R + cbase + nf * 8];
        float2 s2 = *(const float2*)&g_rs[2 * R + cbase + nf * 8];
        n22c[nf * 2] = n2.x; n22c[nf * 2 + 1] = n2.y;
        s2c[nf * 2]  = s2.x; s2c[nf * 2 + 1]  = s2.y;
    }

    // transform to base and store
    #pragma unroll
    for (int mf = 0; mf < 4; mf++) {
        #pragma unroll
        for (int h = 0; h < 2; h++) {
            int row = rbase + mf * 16 + h * 8;
            float n21 = n21r8[mf * 2 + h];
            #pragma unroll
            for (int nf = 0; nf < 4; nf++) {
                float b0 = n21 + n22c[nf * 2]     - 2.0f * acc[mf][nf][h * 2];
                float b1 = n21 + n22c[nf * 2 + 1] - 2.0f * acc[mf][nf][h * 2 + 1];
                acc[mf][nf][h * 2]     = b0;
                acc[mf][nf][h * 2 + 1] = b1;
                float2 o = {b0, b1};
                *(float2*)&g_base[(size_t)row * R + cbase + nf * 8] = o;
            }
        }
    }

    // S accumulation: per k, per row-fragment, sum over this thread's 8 cols,
    // quad-reduce (lanes sharing a row), atomic to g_S.
    #pragma unroll
    for (int k = 0; k < K; k++) {
        const float akt  = skp[k];
        const float nakt = -akt;
        const float bkt  = skp[K + k];
        const float ekc2 = skp[2 * K + k];
        const float lo   = skp[3 * K + k];
        const float hi   = skp[4 * K + k];
        #pragma unroll
        for (int mf = 0; mf < 4; mf++) {
            #pragma unroll
            for (int h = 0; h < 2; h++) {
                const float pi = fmaf(sx1r8[mf * 2 + h], akt, bkt);
                float s = 0.0f;
                #pragma unroll
                for (int nf = 0; nf < 4; nf++) {
                    #pragma unroll
                    for (int e = 0; e < 2; e++) {
                        float arg = fmaf(acc[mf][nf][h * 2 + e], ekc2,
                                         fmaf(s2c[nf * 2 + e], nakt, pi));
                        arg = fminf(fmaxf(arg, lo), hi);
                        s += exp_unit(ex2f(arg));   // = exp(kv)
                    }
                }
                s += __shfl_xor_sync(0xFFFFFFFFu, s, 1);
                s += __shfl_xor_sync(0xFFFFFFFFu, s, 2);
                if ((lane & 3) == 0)
                    atomicAdd(&g_S[k * R + rbase + mf * 16 + h * 8], s);
            }
        }
    }
}

// ---------------------------------------------------------------------------
// Kernel B: one block per row r; recompute numerators from stored base,
// normalize by S, weighted sum over k.
__global__ void __launch_bounds__(256)
kernelB(float* __restrict__ out) {
    const int r = blockIdx.x;
    __shared__ float sa[K], se[K], slo[K], shi[K], sw[K], sp_[K];
    if (threadIdx.x < K) {
        int k = threadIdx.x;
        float akt = g_kp[k];
        sa[k]  = akt;
        se[k]  = g_kp[2 * K + k];
        slo[k] = g_kp[3 * K + k];
        shi[k] = g_kp[4 * K + k];
        sw[k]  = g_kp[5 * K + k] / g_S[k * R + r];
        sp_[k] = fmaf(g_rs[r], akt, g_kp[K + k]);
    }
    __syncthreads();

    float nakt[K], ekc2[K], lo[K], hi[K], wk[K], pr[K];
    #pragma unroll
    for (int k = 0; k < K; k++) {
        nakt[k] = -sa[k]; ekc2[k] = se[k]; lo[k] = slo[k];
        hi[k] = shi[k];   wk[k] = sw[k];   pr[k] = sp_[k];
    }
    const float* baserow = g_base + (size_t)r * R;
    float* outrow = out + (size_t)r * R;

    #pragma unroll
    for (int it = 0; it < R / (256 * 4); it++) {
        int c = (it * 256 + threadIdx.x) * 4;
        float4 b4 = *(const float4*)(baserow + c);
        float4 s4 = *(const float4*)(g_rs + 2 * R + c);
        const float* bb = (const float*)&b4;
        const float* cc = (const float*)&s4;
        float o[4] = {0.0f, 0.0f, 0.0f, 0.0f};
        #pragma unroll
        for (int j = 0; j < 4; j++) {
            #pragma unroll
            for (int k = 0; k < K; k++) {
                float arg = fmaf(bb[j], ekc2[k], fmaf(cc[j], nakt[k], pr[k]));
                arg = fminf(fmaxf(arg, lo[k]), hi[k]);
                o[j] = fmaf(exp_unit(ex2f(arg)), wk[k], o[j]);
            }
        }
        float4 ov = {o[0], o[1], o[2], o[3]};
        *(float4*)(outrow + c) = ov;
    }
}

// ---------------------------------------------------------------------------
extern "C" void kernel_launch(void* const* d_in, const int* in_sizes, int n_in,
                              void* d_out, int out_size) {
    const float* x1   = (const float*)d_in[0];  // [R, F]
    const float* x2   = (const float*)d_in[1];  // [R, F]
    const float* sig  = (const float*)d_in[2];  // [K]
    const float* mean = (const float*)d_in[3];  // [K]
    const float* sp   = (const float*)d_in[4];  // [K]
    float* out = (float*)d_out;                 // [R, R]

    cudaFuncSetAttribute(kernelA, cudaFuncAttributeMaxDynamicSharedMemorySize,
                         A_SMEM);

    params_kernel<<<1, 32>>>(sig, mean, sp);
    zero_S_kernel<<<(K * R + 255) / 256, 256>>>();
    stats_kernel<<<(2 * R) / 8, 256>>>(x1, x2);
    split_kernel<<<(R * F / 4 + 255) / 256, 256>>>(x1, x2);

    dim3 gridA(R / BN, R / BM);
    kernelA<<<gridA, 256, A_SMEM>>>();

    kernelB<<<R, 256>>>(out);
}

// round 10
// speedup vs baseline: 1.2650x; 1.2650x over previous
#include <cuda_runtime.h>
#include <cuda_bf16.h>
#include <cstdint>

#define R 4096
#define F 256
#define K 8
#define CMIN 1e-6f
#define CMAX 1e6f
#define C_BIAS 0.5287663729448977f  /* log2(log2(e)) */

#define BM 128
#define BN 128
#define TILE_B 16384               // one 128row x 128B bf16 tile (BK=64)
#define A_SMEM (4 * TILE_B + 1024)

// Scratch (static device globals — no runtime allocation)
__device__ __align__(16) float g_base[(size_t)R * (size_t)R];  // 64 MB
__device__ __align__(16) float g_S[K * R];
__device__ __align__(16) float g_rs[4 * R];     // sx1 | n2x1 | sx2 | n2x2
__device__ __align__(16) float g_kp[6 * K];     // akt|bkt2|ekc2|lo|hi|nw
__device__ __align__(16) __nv_bfloat16 g_x1h[R * F];
__device__ __align__(16) __nv_bfloat16 g_x1l[R * F];
__device__ __align__(16) __nv_bfloat16 g_x2h[R * F];
__device__ __align__(16) __nv_bfloat16 g_x2l[R * F];

__device__ __forceinline__ uint32_t smem_u32(const void* p) {
    uint32_t a;
    asm("{ .reg .u64 t; cvta.to.shared.u64 t, %1; cvt.u32.u64 %0, t; }"
        : "=r"(a) : "l"(p));
    return a;
}
__device__ __forceinline__ float ex2f(float x) {
    float y;
    asm("ex2.approx.ftz.f32 %0, %1;" : "=f"(y) : "f"(x));
    return y;
}
__device__ __forceinline__ void ldsm_x4(uint32_t* r, uint32_t addr) {
    asm volatile("ldmatrix.sync.aligned.m8n8.x4.shared.b16 {%0,%1,%2,%3}, [%4];"
                 : "=r"(r[0]), "=r"(r[1]), "=r"(r[2]), "=r"(r[3]) : "r"(addr));
}
__device__ __forceinline__ void mma16816(float* c, const uint32_t* a,
                                         uint32_t b0, uint32_t b1) {
    asm volatile(
        "mma.sync.aligned.m16n8k16.row.col.f32.bf16.bf16.f32 "
        "{%0,%1,%2,%3}, {%4,%5,%6,%7}, {%8,%9}, {%0,%1,%2,%3};"
        : "+f"(c[0]), "+f"(c[1]), "+f"(c[2]), "+f"(c[3])
        : "r"(a[0]), "r"(a[1]), "r"(a[2]), "r"(a[3]), "r"(b0), "r"(b1));
}

// ---------------------------------------------------------------------------
// Per-k constants. arg = dist*ekc2 + C_BIAS, ekc2 = -log2e/(2 sigma^2) < 0.
// e^kv = ex2(ex2(arg)). Clamp arg in [CMAX*ekc2+C, CMIN*ekc2+C].
__global__ void params_kernel(const float* __restrict__ sig,
                              const float* __restrict__ mean,
                              const float* __restrict__ sp) {
    if (threadIdx.x == 0) {
        const float L2E = 1.4426950408889634f;
        float w[K];
        float m = -3.4e38f;
        #pragma unroll
        for (int k = 0; k < K; k++) {
            float v = 1.0f / (sp[k] * sp[k]);
            w[k] = v;
            if (v > m) m = v;
        }
        float s = 0.0f;
        #pragma unroll
        for (int k = 0; k < K; k++) { w[k] = __expf(w[k] - m); s += w[k]; }
        float inv_s = 1.0f / s;
        #pragma unroll
        for (int k = 0; k < K; k++) {
            float ekc2 = -L2E / (2.0f * sig[k] * sig[k]);
            float ak   = -2.0f * mean[k];
            float bk   = (float)F * mean[k] * mean[k];
            g_kp[k]         = ak * ekc2;              // akt
            g_kp[K + k]     = bk * ekc2 + C_BIAS;     // bkt2
            g_kp[2 * K + k] = ekc2;
            g_kp[3 * K + k] = CMAX * ekc2 + C_BIAS;   // lo
            g_kp[4 * K + k] = CMIN * ekc2 + C_BIAS;   // hi
            g_kp[5 * K + k] = w[k] * inv_s;           // normalized weight
        }
    }
}

// ---------------------------------------------------------------------------
// Fused prep: zero g_S; one warp per row of x1/x2 computes the bf16 hi/lo
// split (lane-contiguous 8-element chunks, coalesced 16B writes), the row
// sum, and the row squared norm.
__global__ void __launch_bounds__(256)
prep_kernel(const float* __restrict__ x1, const float* __restrict__ x2) {
    const int gid = blockIdx.x * blockDim.x + threadIdx.x;
    if (gid < K * R) g_S[gid] = 0.0f;

    const int w    = gid >> 5;          // 0 .. 2R-1 (grid sized exactly)
    const int lane = gid & 31;
    const bool is1 = (w < R);
    const int row  = is1 ? w : (w - R);
    const float* x = is1 ? x1 : x2;
    __nv_bfloat16* xh = is1 ? g_x1h : g_x2h;
    __nv_bfloat16* xl = is1 ? g_x1l : g_x2l;

    const float* p = x + (size_t)row * F + lane * 8;
    float4 v0 = *(const float4*)p;
    float4 v1 = *(const float4*)(p + 4);
    float vals[8] = {v0.x, v0.y, v0.z, v0.w, v1.x, v1.y, v1.z, v1.w};

    float s = 0.0f, q = 0.0f;
    __nv_bfloat16 hb[8], lb[8];
    #pragma unroll
    for (int e = 0; e < 8; e++) {
        float v = vals[e];
        s += v;
        q = fmaf(v, v, q);
        __nv_bfloat16 h = __float2bfloat16(v);
        hb[e] = h;
        lb[e] = __float2bfloat16(v - __bfloat162float(h));
    }
    *(uint4*)(xh + (size_t)row * F + lane * 8) = *(const uint4*)hb;
    *(uint4*)(xl + (size_t)row * F + lane * 8) = *(const uint4*)lb;

    #pragma unroll
    for (int o = 16; o > 0; o >>= 1) {
        s += __shfl_xor_sync(0xFFFFFFFFu, s, o);
        q += __shfl_xor_sync(0xFFFFFFFFu, q, o);
    }
    if (lane == 0) {
        int off = is1 ? 0 : 2 * R;
        g_rs[off + row]     = s;
        g_rs[off + R + row] = q;
    }
}

// ---------------------------------------------------------------------------
// Kernel A: 128x128 tile, bf16 split-GEMM (hh+hl+lh) via mma.sync m16n8k16.
// 8 warps in 2(m) x 4(n) grid, 64x32 per warp, fp32 register accumulators.
// Epilogue: base transform + store + double-exp S accumulation.
__global__ void __launch_bounds__(256, 2)
kernelA() {
    extern __shared__ char dynsmem[];
    __shared__ float skp[6 * K];

    const int tid  = threadIdx.x;
    const int wid  = tid >> 5;
    const int lane = tid & 31;
    const int wm = wid & 1;          // m position (0..1) -> 64 rows
    const int wn = wid >> 1;         // n position (0..3) -> 32 cols
    const int ln15 = lane & 15;
    const int hi16 = lane >> 4;
    const int r0 = blockIdx.y * BM;
    const int c0 = blockIdx.x * BN;

    const uint32_t dsb = smem_u32(dynsmem);
    const uint32_t tiles_u = (dsb + 1023u) & ~1023u;
    char* tiles = dynsmem + (tiles_u - dsb);

    if (tid < 6 * K) skp[tid] = g_kp[tid];

    // loader mapping: 128 rows x 64 bf16 tiles, SW128 swizzle
    const int lrow  = tid >> 1;
    const int lcol0 = (tid & 1) * 32;
    const __nv_bfloat16* pah = g_x1h + (size_t)(r0 + lrow) * F + lcol0;
    const __nv_bfloat16* pal = g_x1l + (size_t)(r0 + lrow) * F + lcol0;
    const __nv_bfloat16* pbh = g_x2h + (size_t)(c0 + lrow) * F + lcol0;
    const __nv_bfloat16* pbl = g_x2l + (size_t)(c0 + lrow) * F + lcol0;

    // ldmatrix base addresses (row part; chunk xor added per k-step)
    const uint32_t a_row = (uint32_t)(wm * 64 + ln15) * 128u;
    const uint32_t b_row = (uint32_t)(wn * 32 + ln15) * 128u;
    const uint32_t ah_base = tiles_u + 0 * TILE_B + a_row;
    const uint32_t al_base = tiles_u + 1 * TILE_B + a_row;
    const uint32_t bh_base = tiles_u + 2 * TILE_B + b_row;
    const uint32_t bl_base = tiles_u + 3 * TILE_B + b_row;

    float acc[4][4][4];
    #pragma unroll
    for (int i = 0; i < 4; i++)
        #pragma unroll
        for (int j = 0; j < 4; j++)
            #pragma unroll
            for (int c = 0; c < 4; c++) acc[i][j][c] = 0.0f;

    for (int kc = 0; kc < 4; kc++) {
        const int k0 = kc * 64;
        __syncthreads();
        #pragma unroll
        for (int j = 0; j < 4; j++) {
            uint32_t boff = lrow * 128 + (lcol0 + j * 8) * 2;
            uint32_t sw = boff ^ ((boff >> 3) & 0x70);
            *(uint4*)(tiles + 0 * TILE_B + sw) = *(const uint4*)(pah + k0 + j * 8);
            *(uint4*)(tiles + 1 * TILE_B + sw) = *(const uint4*)(pal + k0 + j * 8);
            *(uint4*)(tiles + 2 * TILE_B + sw) = *(const uint4*)(pbh + k0 + j * 8);
            *(uint4*)(tiles + 3 * TILE_B + sw) = *(const uint4*)(pbl + k0 + j * 8);
        }
        __syncthreads();

        #pragma unroll
        for (int ks = 0; ks < 4; ks++) {
            const uint32_t q = (uint32_t)(((ks * 2 + hi16) ^ (ln15 & 7)) * 16);
            uint32_t ah[4][4], bh[2][4], bl[2][4];
            #pragma unroll
            for (int mf = 0; mf < 4; mf++)
                ldsm_x4(ah[mf], ah_base + q + mf * 2048);
            #pragma unroll
            for (int n2 = 0; n2 < 2; n2++)
                ldsm_x4(bh[n2], bh_base + q + n2 * 2048);
            #pragma unroll
            for (int n2 = 0; n2 < 2; n2++)
                ldsm_x4(bl[n2], bl_base + q + n2 * 2048);

            // hh
            #pragma unroll
            for (int mf = 0; mf < 4; mf++)
                #pragma unroll
                for (int nf = 0; nf < 4; nf++)
                    mma16816(acc[mf][nf], ah[mf],
                             bh[nf >> 1][nf & 1], bh[nf >> 1][(nf & 1) + 2]);
            // hl
            #pragma unroll
            for (int mf = 0; mf < 4; mf++)
                #pragma unroll
                for (int nf = 0; nf < 4; nf++)
                    mma16816(acc[mf][nf], ah[mf],
                             bl[nf >> 1][nf & 1], bl[nf >> 1][(nf & 1) + 2]);
            // lh (A-lo overwrites A-hi registers)
            #pragma unroll
            for (int mf = 0; mf < 4; mf++)
                ldsm_x4(ah[mf], al_base + q + mf * 2048);
            #pragma unroll
            for (int mf = 0; mf < 4; mf++)
                #pragma unroll
                for (int nf = 0; nf < 4; nf++)
                    mma16816(acc[mf][nf], ah[mf],
                             bh[nf >> 1][nf & 1], bh[nf >> 1][(nf & 1) + 2]);
        }
    }

    // ---- epilogue ----
    // fragment layout: elem (mf, nf, half, e):
    //   row = r0 + wm*64 + mf*16 + half*8 + lane/4
    //   col = c0 + wn*32 + nf*8 + (lane&3)*2 + e
    const int rbase = r0 + wm * 64 + (lane >> 2);
    const int cbase = c0 + wn * 32 + (lane & 3) * 2;

    float sx1r8[8], n21r8[8];
    #pragma unroll
    for (int i = 0; i < 8; i++) {
        int row = rbase + (i >> 1) * 16 + (i & 1) * 8;
        sx1r8[i] = g_rs[row];
        n21r8[i] = g_rs[R + row];
    }
    float n22c[8], s2c[8];
    #pragma unroll
    for (int nf = 0; nf < 4; nf++) {
        float2 n2 = *(const float2*)&g_rs[3 * R + cbase + nf * 8];
        float2 s2 = *(const float2*)&g_rs[2 * R + cbase + nf * 8];
        n22c[nf * 2] = n2.x; n22c[nf * 2 + 1] = n2.y;
        s2c[nf * 2]  = s2.x; s2c[nf * 2 + 1]  = s2.y;
    }

    // transform to base and store
    #pragma unroll
    for (int mf = 0; mf < 4; mf++) {
        #pragma unroll
        for (int h = 0; h < 2; h++) {
            int row = rbase + mf * 16 + h * 8;
            float n21 = n21r8[mf * 2 + h];
            #pragma unroll
            for (int nf = 0; nf < 4; nf++) {
                float b0 = n21 + n22c[nf * 2]     - 2.0f * acc[mf][nf][h * 2];
                float b1 = n21 + n22c[nf * 2 + 1] - 2.0f * acc[mf][nf][h * 2 + 1];
                acc[mf][nf][h * 2]     = b0;
                acc[mf][nf][h * 2 + 1] = b1;
                float2 o = {b0, b1};
                *(float2*)&g_base[(size_t)row * R + cbase + nf * 8] = o;
            }
        }
    }

    // S accumulation: per k, per row-fragment, sum over this thread's 8 cols,
    // quad-reduce (lanes sharing a row), atomic to g_S.
    #pragma unroll
    for (int k = 0; k < K; k++) {
        const float akt  = skp[k];
        const float nakt = -akt;
        const float bkt2 = skp[K + k];
        const float ekc2 = skp[2 * K + k];
        const float lo   = skp[3 * K + k];
        const float hi   = skp[4 * K + k];
        #pragma unroll
        for (int mf = 0; mf < 4; mf++) {
            #pragma unroll
            for (int h = 0; h < 2; h++) {
                const float pi = fmaf(sx1r8[mf * 2 + h], akt, bkt2);
                float s = 0.0f;
                #pragma unroll
                for (int nf = 0; nf < 4; nf++) {
                    #pragma unroll
                    for (int e = 0; e < 2; e++) {
                        float arg = fmaf(acc[mf][nf][h * 2 + e], ekc2,
                                         fmaf(s2c[nf * 2 + e], nakt, pi));
                        arg = fminf(fmaxf(arg, lo), hi);
                        s += ex2f(ex2f(arg));   // = exp(kv)
                    }
                }
                s += __shfl_xor_sync(0xFFFFFFFFu, s, 1);
                s += __shfl_xor_sync(0xFFFFFFFFu, s, 2);
                if ((lane & 3) == 0)
                    atomicAdd(&g_S[k * R + rbase + mf * 16 + h * 8], s);
            }
        }
    }
}

// ---------------------------------------------------------------------------
// Kernel B: one block per TWO rows; column-side data (g_rs) and the cc*nakt
// product are shared across both rows. Recompute numerators from stored
// base, normalize by S, weighted sum over k.
__global__ void __launch_bounds__(256)
kernelB(float* __restrict__ out) {
    const int r0 = blockIdx.x * 2;
    __shared__ float sa[K], se[K], slo[K], shi[K];
    __shared__ float sw0[K], sw1[K], sp0[K], sp1[K];
    if (threadIdx.x < K) {
        int k = threadIdx.x;
        float akt = g_kp[k];
        float nw  = g_kp[5 * K + k];
        float bkt2 = g_kp[K + k];
        sa[k]  = akt;
        se[k]  = g_kp[2 * K + k];
        slo[k] = g_kp[3 * K + k];
        shi[k] = g_kp[4 * K + k];
        sw0[k] = nw / g_S[k * R + r0];
        sw1[k] = nw / g_S[k * R + r0 + 1];
        sp0[k] = fmaf(g_rs[r0],     akt, bkt2);
        sp1[k] = fmaf(g_rs[r0 + 1], akt, bkt2);
    }
    __syncthreads();

    float nakt[K], ekc2[K], lo[K], hi[K];
    float wk0[K], wk1[K], pr0[K], pr1[K];
    #pragma unroll
    for (int k = 0; k < K; k++) {
        nakt[k] = -sa[k]; ekc2[k] = se[k]; lo[k] = slo[k]; hi[k] = shi[k];
        wk0[k] = sw0[k]; wk1[k] = sw1[k]; pr0[k] = sp0[k]; pr1[k] = sp1[k];
    }
    const float* brow0 = g_base + (size_t)r0 * R;
    const float* brow1 = g_base + (size_t)(r0 + 1) * R;
    float* orow0 = out + (size_t)r0 * R;
    float* orow1 = out + (size_t)(r0 + 1) * R;

    #pragma unroll
    for (int it = 0; it < R / (256 * 4); it++) {
        int c = (it * 256 + threadIdx.x) * 4;
        float4 s4  = *(const float4*)(g_rs + 2 * R + c);
        float4 b40 = *(const float4*)(brow0 + c);
        float4 b41 = *(const float4*)(brow1 + c);
        const float* cc  = (const float*)&s4;
        const float* bb0 = (const float*)&b40;
        const float* bb1 = (const float*)&b41;
        float o0[4] = {0.0f, 0.0f, 0.0f, 0.0f};
        float o1[4] = {0.0f, 0.0f, 0.0f, 0.0f};
        #pragma unroll
        for (int j = 0; j < 4; j++) {
            #pragma unroll
            for (int k = 0; k < K; k++) {
                float t = cc[j] * nakt[k];            // shared by both rows
                float a0 = fmaf(bb0[j], ekc2[k], t + pr0[k]);
                float a1 = fmaf(bb1[j], ekc2[k], t + pr1[k]);
                a0 = fminf(fmaxf(a0, lo[k]), hi[k]);
                a1 = fminf(fmaxf(a1, lo[k]), hi[k]);
                o0[j] = fmaf(ex2f(ex2f(a0)), wk0[k], o0[j]);
                o1[j] = fmaf(ex2f(ex2f(a1)), wk1[k], o1[j]);
            }
        }
        float4 ov0 = {o0[0], o0[1], o0[2], o0[3]};
        float4 ov1 = {o1[0], o1[1], o1[2], o1[3]};
        *(float4*)(orow0 + c) = ov0;
        *(float4*)(orow1 + c) = ov1;
    }
}

// ---------------------------------------------------------------------------
extern "C" void kernel_launch(void* const* d_in, const int* in_sizes, int n_in,
                              void* d_out, int out_size) {
    const float* x1   = (const float*)d_in[0];  // [R, F]
    const float* x2   = (const float*)d_in[1];  // [R, F]
    const float* sig  = (const float*)d_in[2];  // [K]
    const float* mean = (const float*)d_in[3];  // [K]
    const float* sp   = (const float*)d_in[4];  // [K]
    float* out = (float*)d_out;                 // [R, R]

    cudaFuncSetAttribute(kernelA, cudaFuncAttributeMaxDynamicSharedMemorySize,
                         A_SMEM);

    params_kernel<<<1, 32>>>(sig, mean, sp);
    prep_kernel<<<(2 * R) / 8, 256>>>(x1, x2);   // zero S + split + stats

    dim3 gridA(R / BN, R / BM);
    kernelA<<<gridA, 256, A_SMEM>>>();

    kernelB<<<R / 2, 256>>>(out);
}